// round 8
// baseline (speedup 1.0000x reference)
#include <cuda_runtime.h>
#include <math.h>

#define NLOC 196
#define BATCH 512
#define PI_F 3.14159265358979323846f

// ---------------------------------------------------------------------------
// Fused kernel: one block per patch location p (196 blocks, 288 threads).
//   warps 0-7 (256 thr): load 2 samples each + stats partials
//   warp 8 (16 active lanes): builds the fixed post-input-layer 16x16 unitary U
//     CONCURRENTLY with the load/stats phase (only params needed)
//   single __syncthreads joins; every thread finalizes stats redundantly
//   phase 3: warps 0-7 evaluate 2 samples each:
//     s = u0 (x) u1 (x) u2 (x) u3 ; psi = U s ; z_i = sum_k d_i(k) |psi_k|^2
// Bit convention: wire w -> bit (3-w) of state index k.
// ---------------------------------------------------------------------------
__global__ void __launch_bounds__(288, 2) qf_fused(const float* __restrict__ x,
                                                   const float* __restrict__ params,
                                                   float* __restrict__ out) {
    __shared__ float  sU[2][16][16];   // [re/im][k][col]
    __shared__ float2 sPart[8];        // per-warp partial (sum, sumsq)

    const int p = blockIdx.x;
    const int r = p / 14, c = p - r * 14;
    const int base = (2 * r) * 28 + 2 * c;
    const int tid = threadIdx.x;

    float2 a0, a1, b0, b1;

    if (tid < 256) {
        // ---- Phase 1: load 2 samples per thread + stats partials ----
        const float* xb0 = x + tid * 784 + base;
        const float* xb1 = x + (tid + 256) * 784 + base;
        a0 = *reinterpret_cast<const float2*>(xb0);
        a1 = *reinterpret_cast<const float2*>(xb0 + 28);
        b0 = *reinterpret_cast<const float2*>(xb1);
        b1 = *reinterpret_cast<const float2*>(xb1 + 28);

        float sum = (a0.x + a0.y) + (a1.x + a1.y) + (b0.x + b0.y) + (b1.x + b1.y);
        float sq  = a0.x * a0.x + a0.y * a0.y + a1.x * a1.x + a1.y * a1.y
                  + b0.x * b0.x + b0.y * b0.y + b1.x * b1.x + b1.y * b1.y;
        #pragma unroll
        for (int o = 16; o > 0; o >>= 1) {
            sum += __shfl_down_sync(0xffffffffu, sum, o);
            sq  += __shfl_down_sync(0xffffffffu, sq,  o);
        }
        if ((tid & 31) == 0) sPart[tid >> 5] = make_float2(sum, sq);
    } else if (tid < 272) {
        // ---- Warp 8: build U concurrently (depends only on params) ----
        const int col = tid - 256;
        float vr[16], vi[16];
        #pragma unroll
        for (int k = 0; k < 16; k++) { vr[k] = (k == col) ? 1.f : 0.f; vi[k] = 0.f; }

        #pragma unroll
        for (int l = 0; l < 2; l++) {
            // RY(params[l][w][0])
            #pragma unroll
            for (int wi = 0; wi < 4; wi++) {
                float th = params[(l * 4 + wi) * 3 + 0];
                float ss, cc; __sincosf(0.5f * th, &ss, &cc);
                int m = 8 >> wi;
                #pragma unroll
                for (int k = 0; k < 16; k++) if (!(k & m)) {
                    int k1 = k | m;
                    float r0 = vr[k], i0 = vi[k], r1 = vr[k1], i1 = vi[k1];
                    vr[k]  = cc * r0 - ss * r1;  vi[k]  = cc * i0 - ss * i1;
                    vr[k1] = ss * r0 + cc * r1;  vi[k1] = ss * i0 + cc * i1;
                }
            }
            // CNOT(i -> i+1)
            #pragma unroll
            for (int i = 0; i < 3; i++) {
                int cm = 8 >> i, tm = 8 >> (i + 1);
                #pragma unroll
                for (int k = 0; k < 16; k++) if ((k & cm) && !(k & tm)) {
                    int k1 = k | tm;
                    float tr = vr[k], ti = vi[k];
                    vr[k] = vr[k1]; vi[k] = vi[k1]; vr[k1] = tr; vi[k1] = ti;
                }
            }
            // RY(params[l][w][1])
            #pragma unroll
            for (int wi = 0; wi < 4; wi++) {
                float th = params[(l * 4 + wi) * 3 + 1];
                float ss, cc; __sincosf(0.5f * th, &ss, &cc);
                int m = 8 >> wi;
                #pragma unroll
                for (int k = 0; k < 16; k++) if (!(k & m)) {
                    int k1 = k | m;
                    float r0 = vr[k], i0 = vi[k], r1 = vr[k1], i1 = vi[k1];
                    vr[k]  = cc * r0 - ss * r1;  vi[k]  = cc * i0 - ss * i1;
                    vr[k1] = ss * r0 + cc * r1;  vi[k1] = ss * i0 + cc * i1;
                }
            }
            // CNOT(i+1 -> i)
            #pragma unroll
            for (int i = 0; i < 3; i++) {
                int cm = 8 >> (i + 1), tm = 8 >> i;
                #pragma unroll
                for (int k = 0; k < 16; k++) if ((k & cm) && !(k & tm)) {
                    int k1 = k | tm;
                    float tr = vr[k], ti = vi[k];
                    vr[k] = vr[k1]; vi[k] = vi[k1]; vr[k1] = tr; vi[k1] = ti;
                }
            }
            // RZ(params[l][w][2]): |0> *= exp(-i th/2), |1> *= exp(+i th/2)
            #pragma unroll
            for (int wi = 0; wi < 4; wi++) {
                float th = params[(l * 4 + wi) * 3 + 2];
                float ss, cc; __sincosf(0.5f * th, &ss, &cc);
                int m = 8 >> wi;
                #pragma unroll
                for (int k = 0; k < 16; k++) {
                    float rr = vr[k], ii = vi[k];
                    if (k & m) { vr[k] = rr * cc - ii * ss; vi[k] = ii * cc + rr * ss; }
                    else       { vr[k] = rr * cc + ii * ss; vi[k] = ii * cc - rr * ss; }
                }
            }
        }
        #pragma unroll
        for (int k = 0; k < 16; k++) {
            sU[0][k][col] = vr[k];
            sU[1][k][col] = vi[k];
        }
    }

    __syncthreads();
    if (tid >= 256) return;   // U-warp done

    // ---- Stats finalize: redundant per-thread (cheaper than 2nd barrier) ----
    float S = 0.f, Q = 0.f;
    #pragma unroll
    for (int i = 0; i < 8; i++) { float2 pp = sPart[i]; S += pp.x; Q += pp.y; }
    const float mean  = S * (1.f / 2048.f);
    const float ssd   = Q - S * S * (1.f / 2048.f);
    const float sd    = sqrtf(ssd * (1.f / 2047.f));
    const float scale = __fdividef(PI_F, sd + 1e-8f);

    // ---- Phase 3: evaluate both samples, sharing every U load ----
    float sva[16], svb[16];
    {
        float c0, s0, c1, s1, c2, s2, c3, s3;
        __sincosf(0.5f * (a0.x - mean) * scale, &s0, &c0);
        __sincosf(0.5f * (a0.y - mean) * scale, &s1, &c1);
        __sincosf(0.5f * (a1.x - mean) * scale, &s2, &c2);
        __sincosf(0.5f * (a1.y - mean) * scale, &s3, &c3);
        float p00 = c0 * c1, p01 = c0 * s1, p10 = s0 * c1, p11 = s0 * s1;
        float q00 = c2 * c3, q01 = c2 * s3, q10 = s2 * c3, q11 = s2 * s3;
        sva[ 0] = p00 * q00; sva[ 1] = p00 * q01; sva[ 2] = p00 * q10; sva[ 3] = p00 * q11;
        sva[ 4] = p01 * q00; sva[ 5] = p01 * q01; sva[ 6] = p01 * q10; sva[ 7] = p01 * q11;
        sva[ 8] = p10 * q00; sva[ 9] = p10 * q01; sva[10] = p10 * q10; sva[11] = p10 * q11;
        sva[12] = p11 * q00; sva[13] = p11 * q01; sva[14] = p11 * q10; sva[15] = p11 * q11;
    }
    {
        float c0, s0, c1, s1, c2, s2, c3, s3;
        __sincosf(0.5f * (b0.x - mean) * scale, &s0, &c0);
        __sincosf(0.5f * (b0.y - mean) * scale, &s1, &c1);
        __sincosf(0.5f * (b1.x - mean) * scale, &s2, &c2);
        __sincosf(0.5f * (b1.y - mean) * scale, &s3, &c3);
        float p00 = c0 * c1, p01 = c0 * s1, p10 = s0 * c1, p11 = s0 * s1;
        float q00 = c2 * c3, q01 = c2 * s3, q10 = s2 * c3, q11 = s2 * s3;
        svb[ 0] = p00 * q00; svb[ 1] = p00 * q01; svb[ 2] = p00 * q10; svb[ 3] = p00 * q11;
        svb[ 4] = p01 * q00; svb[ 5] = p01 * q01; svb[ 6] = p01 * q10; svb[ 7] = p01 * q11;
        svb[ 8] = p10 * q00; svb[ 9] = p10 * q01; svb[10] = p10 * q10; svb[11] = p10 * q11;
        svb[12] = p11 * q00; svb[13] = p11 * q01; svb[14] = p11 * q10; svb[15] = p11 * q11;
    }

    float za0 = 0.f, za1 = 0.f, za2 = 0.f, za3 = 0.f;
    float zb0 = 0.f, zb1 = 0.f, zb2 = 0.f, zb3 = 0.f;
    #pragma unroll
    for (int k = 0; k < 16; k++) {
        const float4* ur = reinterpret_cast<const float4*>(&sU[0][k][0]);
        const float4* ui = reinterpret_cast<const float4*>(&sU[1][k][0]);
        float pra = 0.f, pia = 0.f, prb = 0.f, pib = 0.f;
        #pragma unroll
        for (int j = 0; j < 4; j++) {
            float4 r4 = ur[j], i4 = ui[j];
            pra = fmaf(r4.x, sva[4*j+0], fmaf(r4.y, sva[4*j+1],
                  fmaf(r4.z, sva[4*j+2], fmaf(r4.w, sva[4*j+3], pra))));
            pia = fmaf(i4.x, sva[4*j+0], fmaf(i4.y, sva[4*j+1],
                  fmaf(i4.z, sva[4*j+2], fmaf(i4.w, sva[4*j+3], pia))));
            prb = fmaf(r4.x, svb[4*j+0], fmaf(r4.y, svb[4*j+1],
                  fmaf(r4.z, svb[4*j+2], fmaf(r4.w, svb[4*j+3], prb))));
            pib = fmaf(i4.x, svb[4*j+0], fmaf(i4.y, svb[4*j+1],
                  fmaf(i4.z, svb[4*j+2], fmaf(i4.w, svb[4*j+3], pib))));
        }
        float pka = pra * pra + pia * pia;
        float pkb = prb * prb + pib * pib;
        if (k & 8) { za0 -= pka; zb0 -= pkb; } else { za0 += pka; zb0 += pkb; }
        if (k & 4) { za1 -= pka; zb1 -= pkb; } else { za1 += pka; zb1 += pkb; }
        if (k & 2) { za2 -= pka; zb2 -= pkb; } else { za2 += pka; zb2 += pkb; }
        if (k & 1) { za3 -= pka; zb3 -= pkb; } else { za3 += pka; zb3 += pkb; }
    }

    // out[b, p*4 + i] — 16B aligned float4 stores
    *reinterpret_cast<float4*>(out + tid * 784 + p * 4)         = make_float4(za0, za1, za2, za3);
    *reinterpret_cast<float4*>(out + (tid + 256) * 784 + p * 4) = make_float4(zb0, zb1, zb2, zb3);
}

extern "C" void kernel_launch(void* const* d_in, const int* in_sizes, int n_in,
                              void* d_out, int out_size) {
    const float* x      = (const float*)d_in[0];   // (512, 28, 28)
    const float* params = (const float*)d_in[1];   // (2, 4, 3)
    float* out          = (float*)d_out;           // (512, 784)

    qf_fused<<<NLOC, 288>>>(x, params, out);
}

// round 10
// speedup vs baseline: 1.5038x; 1.5038x over previous
#include <cuda_runtime.h>
#include <math.h>

#define NLOC 196
#define BATCH 512
#define PI_F 3.14159265358979323846f

// ---------------------------------------------------------------------------
// Fused kernel: one block per patch location p (196 blocks, 256 threads).
// Each block: loads its 512 samples (2/thread), reduces normalization stats,
// 16 threads build the fixed post-input-layer 16x16 unitary U into shared,
// then every thread evaluates 2 samples:
//   s = u0 (x) u1 (x) u2 (x) u3  (real product state from input RY layer)
//   psi = U s;  z_i = sum_k d_i(k) |psi_k|^2
// Bit convention: wire w -> bit (3-w) of state index k.
// All transcendentals via MUFU fast path (tolerance 1e-3, we are at ~5e-6).
// ---------------------------------------------------------------------------
__global__ void __launch_bounds__(256, 2) qf_fused(const float* __restrict__ x,
                                                   const float* __restrict__ params,
                                                   float* __restrict__ out) {
    __shared__ float sU[2][16][16];   // [re/im][k][col]
    __shared__ float sPart[2][8];     // per-warp partial (sum, sumsq)
    __shared__ float sStat[2];        // mean, pi/(sd+1e-8)

    const int p = blockIdx.x;
    const int r = p / 14, c = p - r * 14;
    const int base = (2 * r) * 28 + 2 * c;
    const int tid = threadIdx.x;

    // ---- Phase 1: load 2 samples per thread + stats partials ----
    const float* xb0 = x + tid * 784 + base;
    const float* xb1 = x + (tid + 256) * 784 + base;
    float2 a0 = *reinterpret_cast<const float2*>(xb0);
    float2 a1 = *reinterpret_cast<const float2*>(xb0 + 28);
    float2 b0 = *reinterpret_cast<const float2*>(xb1);
    float2 b1 = *reinterpret_cast<const float2*>(xb1 + 28);

    float sum = (a0.x + a0.y) + (a1.x + a1.y) + (b0.x + b0.y) + (b1.x + b1.y);
    float sq  = a0.x * a0.x + a0.y * a0.y + a1.x * a1.x + a1.y * a1.y
              + b0.x * b0.x + b0.y * b0.y + b1.x * b1.x + b1.y * b1.y;
    #pragma unroll
    for (int o = 16; o > 0; o >>= 1) {
        sum += __shfl_down_sync(0xffffffffu, sum, o);
        sq  += __shfl_down_sync(0xffffffffu, sq,  o);
    }
    int lane = tid & 31, w = tid >> 5;
    if (lane == 0) { sPart[0][w] = sum; sPart[1][w] = sq; }
    __syncthreads();

    // ---- Phase 2 (concurrent): warp 7 finalizes stats, warp 0 builds U ----
    if (tid == 224) {
        float S = 0.f, Q = 0.f;
        #pragma unroll
        for (int i = 0; i < 8; i++) { S += sPart[0][i]; Q += sPart[1][i]; }
        const float n = 2048.f;
        float mean = S / n;
        float ssd  = Q - S * S / n;
        float sd   = sqrtf(ssd / (n - 1.f));
        sStat[0] = mean;
        sStat[1] = __fdividef(PI_F, sd + 1e-8f);
    }
    if (tid < 16) {
        const int col = tid;
        float vr[16], vi[16];
        #pragma unroll
        for (int k = 0; k < 16; k++) { vr[k] = (k == col) ? 1.f : 0.f; vi[k] = 0.f; }

        #pragma unroll
        for (int l = 0; l < 2; l++) {
            // RY(params[l][w][0])
            #pragma unroll
            for (int wi = 0; wi < 4; wi++) {
                float th = params[(l * 4 + wi) * 3 + 0];
                float ss, cc; __sincosf(0.5f * th, &ss, &cc);
                int m = 8 >> wi;
                #pragma unroll
                for (int k = 0; k < 16; k++) if (!(k & m)) {
                    int k1 = k | m;
                    float r0 = vr[k], i0 = vi[k], r1 = vr[k1], i1 = vi[k1];
                    vr[k]  = cc * r0 - ss * r1;  vi[k]  = cc * i0 - ss * i1;
                    vr[k1] = ss * r0 + cc * r1;  vi[k1] = ss * i0 + cc * i1;
                }
            }
            // CNOT(i -> i+1)
            #pragma unroll
            for (int i = 0; i < 3; i++) {
                int cm = 8 >> i, tm = 8 >> (i + 1);
                #pragma unroll
                for (int k = 0; k < 16; k++) if ((k & cm) && !(k & tm)) {
                    int k1 = k | tm;
                    float tr = vr[k], ti = vi[k];
                    vr[k] = vr[k1]; vi[k] = vi[k1]; vr[k1] = tr; vi[k1] = ti;
                }
            }
            // RY(params[l][w][1])
            #pragma unroll
            for (int wi = 0; wi < 4; wi++) {
                float th = params[(l * 4 + wi) * 3 + 1];
                float ss, cc; __sincosf(0.5f * th, &ss, &cc);
                int m = 8 >> wi;
                #pragma unroll
                for (int k = 0; k < 16; k++) if (!(k & m)) {
                    int k1 = k | m;
                    float r0 = vr[k], i0 = vi[k], r1 = vr[k1], i1 = vi[k1];
                    vr[k]  = cc * r0 - ss * r1;  vi[k]  = cc * i0 - ss * i1;
                    vr[k1] = ss * r0 + cc * r1;  vi[k1] = ss * i0 + cc * i1;
                }
            }
            // CNOT(i+1 -> i)
            #pragma unroll
            for (int i = 0; i < 3; i++) {
                int cm = 8 >> (i + 1), tm = 8 >> i;
                #pragma unroll
                for (int k = 0; k < 16; k++) if ((k & cm) && !(k & tm)) {
                    int k1 = k | tm;
                    float tr = vr[k], ti = vi[k];
                    vr[k] = vr[k1]; vi[k] = vi[k1]; vr[k1] = tr; vi[k1] = ti;
                }
            }
            // RZ(params[l][w][2]): |0> *= exp(-i th/2), |1> *= exp(+i th/2)
            #pragma unroll
            for (int wi = 0; wi < 4; wi++) {
                float th = params[(l * 4 + wi) * 3 + 2];
                float ss, cc; __sincosf(0.5f * th, &ss, &cc);
                int m = 8 >> wi;
                #pragma unroll
                for (int k = 0; k < 16; k++) {
                    float rr = vr[k], ii = vi[k];
                    if (k & m) { vr[k] = rr * cc - ii * ss; vi[k] = ii * cc + rr * ss; }
                    else       { vr[k] = rr * cc + ii * ss; vi[k] = ii * cc - rr * ss; }
                }
            }
        }
        #pragma unroll
        for (int k = 0; k < 16; k++) {
            sU[0][k][col] = vr[k];
            sU[1][k][col] = vi[k];
        }
    }
    __syncthreads();

    // ---- Phase 3: evaluate both samples, sharing every U load ----
    const float mean = sStat[0], scale = sStat[1];

    float sva[16], svb[16];
    {
        float c0, s0, c1, s1, c2, s2, c3, s3;
        __sincosf(0.5f * (a0.x - mean) * scale, &s0, &c0);
        __sincosf(0.5f * (a0.y - mean) * scale, &s1, &c1);
        __sincosf(0.5f * (a1.x - mean) * scale, &s2, &c2);
        __sincosf(0.5f * (a1.y - mean) * scale, &s3, &c3);
        float p00 = c0 * c1, p01 = c0 * s1, p10 = s0 * c1, p11 = s0 * s1;
        float q00 = c2 * c3, q01 = c2 * s3, q10 = s2 * c3, q11 = s2 * s3;
        sva[ 0] = p00 * q00; sva[ 1] = p00 * q01; sva[ 2] = p00 * q10; sva[ 3] = p00 * q11;
        sva[ 4] = p01 * q00; sva[ 5] = p01 * q01; sva[ 6] = p01 * q10; sva[ 7] = p01 * q11;
        sva[ 8] = p10 * q00; sva[ 9] = p10 * q01; sva[10] = p10 * q10; sva[11] = p10 * q11;
        sva[12] = p11 * q00; sva[13] = p11 * q01; sva[14] = p11 * q10; sva[15] = p11 * q11;
    }
    {
        float c0, s0, c1, s1, c2, s2, c3, s3;
        __sincosf(0.5f * (b0.x - mean) * scale, &s0, &c0);
        __sincosf(0.5f * (b0.y - mean) * scale, &s1, &c1);
        __sincosf(0.5f * (b1.x - mean) * scale, &s2, &c2);
        __sincosf(0.5f * (b1.y - mean) * scale, &s3, &c3);
        float p00 = c0 * c1, p01 = c0 * s1, p10 = s0 * c1, p11 = s0 * s1;
        float q00 = c2 * c3, q01 = c2 * s3, q10 = s2 * c3, q11 = s2 * s3;
        svb[ 0] = p00 * q00; svb[ 1] = p00 * q01; svb[ 2] = p00 * q10; svb[ 3] = p00 * q11;
        svb[ 4] = p01 * q00; svb[ 5] = p01 * q01; svb[ 6] = p01 * q10; svb[ 7] = p01 * q11;
        svb[ 8] = p10 * q00; svb[ 9] = p10 * q01; svb[10] = p10 * q10; svb[11] = p10 * q11;
        svb[12] = p11 * q00; svb[13] = p11 * q01; svb[14] = p11 * q10; svb[15] = p11 * q11;
    }

    float za0 = 0.f, za1 = 0.f, za2 = 0.f, za3 = 0.f;
    float zb0 = 0.f, zb1 = 0.f, zb2 = 0.f, zb3 = 0.f;
    #pragma unroll
    for (int k = 0; k < 16; k++) {
        const float4* ur = reinterpret_cast<const float4*>(&sU[0][k][0]);
        const float4* ui = reinterpret_cast<const float4*>(&sU[1][k][0]);
        float pra = 0.f, pia = 0.f, prb = 0.f, pib = 0.f;
        #pragma unroll
        for (int j = 0; j < 4; j++) {
            float4 r4 = ur[j], i4 = ui[j];
            pra = fmaf(r4.x, sva[4*j+0], fmaf(r4.y, sva[4*j+1],
                  fmaf(r4.z, sva[4*j+2], fmaf(r4.w, sva[4*j+3], pra))));
            pia = fmaf(i4.x, sva[4*j+0], fmaf(i4.y, sva[4*j+1],
                  fmaf(i4.z, sva[4*j+2], fmaf(i4.w, sva[4*j+3], pia))));
            prb = fmaf(r4.x, svb[4*j+0], fmaf(r4.y, svb[4*j+1],
                  fmaf(r4.z, svb[4*j+2], fmaf(r4.w, svb[4*j+3], prb))));
            pib = fmaf(i4.x, svb[4*j+0], fmaf(i4.y, svb[4*j+1],
                  fmaf(i4.z, svb[4*j+2], fmaf(i4.w, svb[4*j+3], pib))));
        }
        float pka = pra * pra + pia * pia;
        float pkb = prb * prb + pib * pib;
        if (k & 8) { za0 -= pka; zb0 -= pkb; } else { za0 += pka; zb0 += pkb; }
        if (k & 4) { za1 -= pka; zb1 -= pkb; } else { za1 += pka; zb1 += pkb; }
        if (k & 2) { za2 -= pka; zb2 -= pkb; } else { za2 += pka; zb2 += pkb; }
        if (k & 1) { za3 -= pka; zb3 -= pkb; } else { za3 += pka; zb3 += pkb; }
    }

    // out[b, p*4 + i] — 16B aligned float4 stores
    *reinterpret_cast<float4*>(out + tid * 784 + p * 4)         = make_float4(za0, za1, za2, za3);
    *reinterpret_cast<float4*>(out + (tid + 256) * 784 + p * 4) = make_float4(zb0, zb1, zb2, zb3);
}

extern "C" void kernel_launch(void* const* d_in, const int* in_sizes, int n_in,
                              void* d_out, int out_size) {
    const float* x      = (const float*)d_in[0];   // (512, 28, 28)
    const float* params = (const float*)d_in[1];   // (2, 4, 3)
    float* out          = (float*)d_out;           // (512, 784)

    qf_fused<<<NLOC, 256>>>(x, params, out);
}